// round 13
// baseline (speedup 1.0000x reference)
#include <cuda_runtime.h>
#include <cstddef>

#define B 16
#define N 1024
#define P 256
#define D 64
#define K 26

#define PROD_CTAS 128        // importance producer CTAs (bids 0..127)
#define STREAM_CTAS 2048     // persistent streamer CTAs
#define NCHUNK 8             // n-chunks per p per batch (CTA c: nc = c&7)
#define NPERHW 16            // n per half-warp per batch
#define KD4 (K * D / 4)      // 416 float4 per anchor block
#define SHARE 208            // float4 of output per CTA per batch (425984/2048)

// ---- scratch (no allocations allowed; device globals) ----
__device__ float g_importance[N];                // [n]
__device__ float g_pscore[B * P * NCHUNK];       // partial scores
__device__ float g_pmean[B * P * NCHUNK * D];    // partial means (8.4 MB)
__device__ float g_anchor[B * K * D];            // finalized anchors
__device__ int   g_done;                         // producer counter
__device__ int   g_cnt[B];                       // per-batch arrival counters
__device__ int   g_ready[B];                     // per-batch anchor-ready flags
__device__ int   g_fin;                          // retire counter (drives reset)

// ------------------------------------------------------------------
// ONE persistent kernel, batch-pipelined.
//  bid < 128: PRODUCER — importance cols, publish, bump g_done, exit.
//  else: STREAMER CTA c = bid-128: owns (p = c>>3, nc = c&7).
//    Loop b = 0..15:
//      * stream batch b's 128 n's for p (8 half-warps x 16 n, 256B
//        contiguous per half-warp load; 8192 warps chip-wide = the
//        empirically required saturation count)
//      * CTA-reduce partial mean + score, write partials, arrive at
//        g_cnt[b]; LAST arriver finalizes batch b (deterministic
//        fixed-order reduce -> stable rank-count top-k matching
//        jax.lax.top_k (descending, low index wins ties) -> anchor)
//        and sets g_ready[b]
//      * write this CTA's 3.3KB share of batch b-1's OUTPUT
//        (overlaps next batch's reads -> hides the 109MB write)
//    After loop: write share of batch 15; 2048th retiree resets
//    counters for the next graph replay.
// Deadlock-free: producers never wait; arrivals never block; ready[x]
// waits only on co-resident CTAs that are making progress.
// ------------------------------------------------------------------
__global__ void __launch_bounds__(128, 15)
k_all(const float* __restrict__ patches,
      const float* __restrict__ adp,
      float* __restrict__ out) {
    __shared__ float4 red[8][16];     // cross-half-warp mean reduce
    __shared__ float  ssc[8];         // per-half-warp partial scores
    __shared__ float  prodred[16][8]; // producer reduce
    __shared__ float  sc[P];          // finalizer: reduced scores
    __shared__ int    tk[K];          // finalizer: top-k indices
    __shared__ int    s_islast;

    int tid = threadIdx.x;
    int bid = blockIdx.x;

    if (bid < PROD_CTAS) {
        // ---------------- producer: 8 columns of adp ----------------
        int jl   = tid & 7;
        int iseg = tid >> 3;             // 0..15, 64 rows each
        int j    = bid * 8 + jl;
        float s = 0.f;
        const float* col = adp + (size_t)(iseg * 64) * N + j;
#pragma unroll 8
        for (int i = 0; i < 64; i++) s += col[(size_t)i * N];
        prodred[iseg][jl] = s;
        __syncthreads();
        if (tid < 8) {
            float t = 0.f;
#pragma unroll
            for (int r = 0; r < 16; r++) t += prodred[r][tid];
            g_importance[j - jl + tid] = t * (1.0f / (float)N);
        }
        __threadfence();
        __syncthreads();
        if (tid == 0) atomicAdd(&g_done, 1);
        return;
    }

    // ---------------- persistent streamer ----------------
    int c  = bid - PROD_CTAS;            // 0..2047
    int p  = c >> 3;                     // patch index (CTA-uniform)
    int nc = c & 7;                      // n-chunk (CTA-uniform)
    int hw = tid >> 4;                   // half-warp 0..7
    int hl = tid & 15;                   // lane in half-warp (d-quarter)
    int nbase = nc * 128 + hw * NPERHW;  // first n of this half-warp (all b)

    const size_t nstrideF4 = (size_t)P * D / 4;     // 4096 float4 per n
    float myimp = 0.f;                   // imp[nbase+hl], loaded once (b==0)

    // output-share geometry (same every batch)
    int slot = c >> 1;                   // n-slot within batch
    int off0 = (c & 1) * SHARE;          // first/second half of the slot

    for (int b = 0; b < B; b++) {
        // ---- stream this batch's slice ----
        const float4* base = (const float4*)patches
            + ((size_t)(b * N + nbase) * P + p) * (D / 4) + hl;
        float4 ms = make_float4(0.f, 0.f, 0.f, 0.f);
        float mynorm = 0.f;
#pragma unroll
        for (int i = 0; i < NPERHW; i++) {
            float4 v = __ldcs(base + (size_t)i * nstrideF4);
            ms.x += v.x; ms.y += v.y; ms.z += v.z; ms.w += v.w;
            float sq = v.x * v.x + v.y * v.y + v.z * v.z + v.w * v.w;
            sq += __shfl_xor_sync(0xffffffffu, sq, 8);
            sq += __shfl_xor_sync(0xffffffffu, sq, 4);
            sq += __shfl_xor_sync(0xffffffffu, sq, 2);
            sq += __shfl_xor_sync(0xffffffffu, sq, 1);
            mynorm = (hl == i) ? sqrtf(sq) : mynorm;   // lane hl owns n=nbase+hl
        }

        if (b == 0) {                    // producers finished ~8us ago
            if (tid == 0) {
                while (*(volatile int*)&g_done != PROD_CTAS) { __nanosleep(100); }
            }
            __syncthreads();
            __threadfence();             // acquire importance
            myimp = __ldg(&g_importance[nbase + hl]);
        }

        // per-half-warp partial score
        float acc = mynorm * myimp;
        acc += __shfl_xor_sync(0xffffffffu, acc, 8);
        acc += __shfl_xor_sync(0xffffffffu, acc, 4);
        acc += __shfl_xor_sync(0xffffffffu, acc, 2);
        acc += __shfl_xor_sync(0xffffffffu, acc, 1);

        // ---- CTA reduce + partial writes ----
        __syncthreads();                 // smem reuse guard
        red[hw][hl] = ms;
        if (hl == 0) ssc[hw] = acc;
        __syncthreads();
        if (tid < 16) {
            float4 m = make_float4(0.f, 0.f, 0.f, 0.f);
#pragma unroll
            for (int h = 0; h < 8; h++) {
                float4 v = red[h][tid];
                m.x += v.x; m.y += v.y; m.z += v.z; m.w += v.w;
            }
            ((float4*)g_pmean)[(((size_t)b * P + p) * NCHUNK + nc) * 16 + tid] = m;
        }
        if (tid == 0) {
            float s = 0.f;
#pragma unroll
            for (int h = 0; h < 8; h++) s += ssc[h];
            g_pscore[((size_t)b * P + p) * NCHUNK + nc] = s;
        }
        __threadfence();                 // publish partials
        __syncthreads();
        if (tid == 0) {
            int old = atomicAdd(&g_cnt[b], 1);
            s_islast = (old == STREAM_CTAS - 1);
        }
        __syncthreads();

        // ---- finalizer (last arriver of batch b) ----
        if (s_islast) {
            __threadfence();             // acquire all batch-b partials
            for (int pp = tid; pp < P; pp += 128) {
                float v = 0.f;
#pragma unroll
                for (int n2 = 0; n2 < NCHUNK; n2++)
                    v += g_pscore[((size_t)b * P + pp) * NCHUNK + n2];
                sc[pp] = v;
            }
            __syncthreads();
            for (int pp = tid; pp < P; pp += 128) {
                float my = sc[pp];
                int rank = 0;
#pragma unroll 8
                for (int q = 0; q < P; q++) {
                    float v = sc[q];
                    rank += (v > my) || (v == my && q < pp);
                }
                if (rank < K) tk[rank] = pp;
            }
            __syncthreads();
            const float inv = 1.0f / (float)N;
            for (int t = tid; t < KD4; t += 128) {
                int kk  = t >> 4;
                int dd4 = t & 15;
                size_t pb = ((size_t)b * P + tk[kk]) * NCHUNK;
                float4 a = make_float4(0.f, 0.f, 0.f, 0.f);
#pragma unroll
                for (int n2 = 0; n2 < NCHUNK; n2++) {
                    float4 v = ((const float4*)g_pmean)[(pb + n2) * 16 + dd4];
                    a.x += v.x; a.y += v.y; a.z += v.z; a.w += v.w;
                }
                ((float4*)g_anchor)[(size_t)b * KD4 + t] =
                    make_float4(a.x * inv, a.y * inv, a.z * inv, a.w * inv);
            }
            __threadfence();
            __syncthreads();
            if (tid == 0) atomicExch(&g_ready[b], 1);
        }

        // ---- write share of batch b-1's OUTPUT (overlaps next reads) ----
        if (b > 0) {
            int bb = b - 1;
            if (tid == 0) {
                while (*(volatile int*)&g_ready[bb] == 0) { __nanosleep(100); }
            }
            __syncthreads();
            __threadfence();             // acquire g_anchor[bb]
            const float4* anc = (const float4*)g_anchor + (size_t)bb * KD4;
            float4* o = (float4*)out + ((size_t)bb * N + slot) * KD4 + off0;
            float4 v0 = anc[off0 + tid];
            __stcs(o + tid, v0);
            if (tid < SHARE - 128) {
                float4 v1 = anc[off0 + tid + 128];
                __stcs(o + tid + 128, v1);
            }
        }
    }

    // ---- final batch's output share ----
    {
        int bb = B - 1;
        if (tid == 0) {
            while (*(volatile int*)&g_ready[bb] == 0) { __nanosleep(100); }
        }
        __syncthreads();
        __threadfence();
        const float4* anc = (const float4*)g_anchor + (size_t)bb * KD4;
        float4* o = (float4*)out + ((size_t)bb * N + slot) * KD4 + off0;
        float4 v0 = anc[off0 + tid];
        __stcs(o + tid, v0);
        if (tid < SHARE - 128) {
            float4 v1 = anc[off0 + tid + 128];
            __stcs(o + tid + 128, v1);
        }
    }

    // ---- retire + counter reset for next replay ----
    __syncthreads();
    if (tid == 0) {
        int o = atomicAdd(&g_fin, 1);
        if (o == STREAM_CTAS - 1) {      // every CTA passed all spins
            g_done = 0;
            g_fin  = 0;
#pragma unroll
            for (int i = 0; i < B; i++) { g_cnt[i] = 0; g_ready[i] = 0; }
            __threadfence();
        }
    }
}

// ------------------------------------------------------------------
extern "C" void kernel_launch(void* const* d_in, const int* in_sizes, int n_in,
                              void* d_out, int out_size) {
    const float* patches = (const float*)d_in[0];
    const float* adp     = (const float*)d_in[1];
    if (n_in >= 2 && in_sizes[0] == N * N && in_sizes[1] == B * N * P * D) {
        const float* t = patches; patches = adp; adp = t;
    }
    float* out = (float*)d_out;

    k_all<<<PROD_CTAS + STREAM_CTAS, 128>>>(patches, adp, out);
}

// round 14
// speedup vs baseline: 2.3426x; 2.3426x over previous
#include <cuda_runtime.h>
#include <cstddef>

#define B 16
#define N 1024
#define P 256
#define D 64
#define K 26
#define S 4                 // n-segments (8192 streaming warps - proven optimum)
#define NSEG (N / S)        // 256 n per segment

#define KD4 (K * D / 4)     // 416 float4 per anchor block

// ---- scratch (no allocations allowed; device globals) ----
__device__ float g_importance[N];            // [n]
__device__ float g_pscore[S * B * P];        // [s, b*P+p] partial scores
__device__ float g_pmean[S * B * P * D];     // [s, b*P+p, d] partial sums
__device__ float g_anchor[B * K * D];        // [b, k, d] finalized anchors

// ------------------------------------------------------------------
// Kernel 1: importance[j] = mean_i adp[i, j]
// 128 CTAs x 128 thr: 8 cols per CTA (lanes 0..7 -> 32B sectors),
// 16 i-segments of 64 rows. Latency-optimized small kernel.
// ------------------------------------------------------------------
__global__ void __launch_bounds__(128) k_importance(const float* __restrict__ adp) {
    __shared__ float red[16][8];
    int jl   = threadIdx.x & 7;
    int iseg = threadIdx.x >> 3;             // 0..15, 64 rows each
    int j    = blockIdx.x * 8 + jl;

    float s = 0.f;
    const float* col = adp + (size_t)(iseg * 64) * N + j;
#pragma unroll 8
    for (int i = 0; i < 64; i++) s += col[(size_t)i * N];
    red[iseg][jl] = s;
    __syncthreads();
    if (threadIdx.x < 8) {
        float t = 0.f;
#pragma unroll
        for (int r = 0; r < 16; r++) t += red[r][threadIdx.x];
        g_importance[j - jl + threadIdx.x] = t * (1.0f / (float)N);
    }
}

// ------------------------------------------------------------------
// Kernel 2: the proven-fastest streaming pass (R8 structure, ~173us).
// n-split into S=4 segments; one HALF-WARP per (seg,b,p): 16 lanes x
// float4 = d=64; the two half-warps of a warp take adjacent p -> each
// warp iteration reads a fully contiguous 512B block. 2048 CTAs x 128
// = 8192 warps. Direct score accumulation (no smem stash), __ldcs
// evict-first loads so the streaming GB doesn't displace L2-resident
// output/scratch.
// ------------------------------------------------------------------
__global__ void __launch_bounds__(128) k_main(const float* __restrict__ patches) {
    int gwarp = (blockIdx.x * blockDim.x + threadIdx.x) >> 5;   // 0 .. S*B*P/2-1
    int lane = threadIdx.x & 31;
    int half = lane >> 4;
    int hl   = lane & 15;

    int seg   = gwarp / (B * (P / 2));
    int rem   = gwarp % (B * (P / 2));
    int b     = rem / (P / 2);
    int p     = (rem % (P / 2)) * 2 + half;
    int n0    = seg * NSEG;

    const float4* base =
        (const float4*)(patches + (((size_t)b * N + n0) * P + p) * (size_t)D) + hl;
    const size_t nstride = (size_t)P * D / 4;   // float4 per n
    const float* imp = g_importance + n0;

    float4 ms = make_float4(0.f, 0.f, 0.f, 0.f);
    float score = 0.f;

#pragma unroll 8
    for (int n = 0; n < NSEG; n++) {
        float4 v = __ldcs(base + (size_t)n * nstride);   // streaming, read-once
        ms.x += v.x; ms.y += v.y; ms.z += v.z; ms.w += v.w;
        float sq = v.x * v.x + v.y * v.y + v.z * v.z + v.w * v.w;
        sq += __shfl_xor_sync(0xffffffffu, sq, 8);
        sq += __shfl_xor_sync(0xffffffffu, sq, 4);
        sq += __shfl_xor_sync(0xffffffffu, sq, 2);
        sq += __shfl_xor_sync(0xffffffffu, sq, 1);
        score += sqrtf(sq) * __ldg(imp + n);
    }

    size_t bp = (size_t)b * P + p;
    ((float4*)g_pmean)[((size_t)seg * B * P + bp) * (D / 4) + hl] = ms;
    if (hl == 0) g_pscore[(size_t)seg * B * P + bp] = score;
}

// ------------------------------------------------------------------
// Kernel 3: per-batch finalize (16 CTAs x 256 thr, ~3.5us):
// score reduce (fixed order -> deterministic) -> stable rank-count
// top-k (matches jax.lax.top_k: descending, lower index wins ties)
// -> anchor reduce + 1/N scale -> g_anchor[b] (stays L2-hot).
// ------------------------------------------------------------------
__global__ void __launch_bounds__(256) k_finalize() {
    __shared__ float sc[P];
    __shared__ int   tk[K];
    int b   = blockIdx.x;
    int tid = threadIdx.x;

    {
        float v = 0.f;
#pragma unroll
        for (int s = 0; s < S; s++) v += g_pscore[s * B * P + b * P + tid];
        sc[tid] = v;
    }
    __syncthreads();

    {
        float my = sc[tid];
        int rank = 0;
#pragma unroll 8
        for (int q = 0; q < P; q++) {
            float v = sc[q];
            rank += (v > my) || (v == my && q < tid);
        }
        if (rank < K) tk[rank] = tid;
    }
    __syncthreads();

    const int MF4 = B * P * D / 4;
    const float inv = 1.0f / (float)N;
    for (int t = tid; t < KD4; t += 256) {
        int kk  = t >> 4;
        int dd4 = t & 15;
        size_t idx = ((size_t)b * P + tk[kk]) * (D / 4) + dd4;
        float4 a = make_float4(0.f, 0.f, 0.f, 0.f);
#pragma unroll
        for (int s = 0; s < S; s++) {
            float4 v = ((const float4*)g_pmean)[(size_t)s * MF4 + idx];
            a.x += v.x; a.y += v.y; a.z += v.z; a.w += v.w;
        }
        ((float4*)g_anchor)[(size_t)b * KD4 + t] =
            make_float4(a.x * inv, a.y * inv, a.z * inv, a.w * inv);
    }
}

// ------------------------------------------------------------------
// Kernel 4: pure replicator. Each thread holds <=2 float4 of batch b's
// anchor block (L2-hot, 6.6KB) and writes 16 n-replicas with PLAIN
// write-back stores: the 109MB output fits in the 126MB L2, so dirty
// lines can be re-overwritten across graph replays without full DRAM
// writeback (the __ldcs streaming reads are evict-first and leave the
// write-back data resident).
// ------------------------------------------------------------------
#define NN_PER_BLOCK 16

__global__ void __launch_bounds__(256) k_out(float* __restrict__ out) {
    const int chunks = N / NN_PER_BLOCK;          // 64
    int b = blockIdx.x / chunks;
    int c = blockIdx.x % chunks;
    int tid = threadIdx.x;

    int t0 = tid;
    int t1 = tid + 256;
    float4 v0 = ((const float4*)g_anchor)[(size_t)b * KD4 + t0];
    float4 v1 = (t1 < KD4) ? ((const float4*)g_anchor)[(size_t)b * KD4 + t1]
                           : make_float4(0, 0, 0, 0);

    float4* obase = (float4*)out + ((size_t)b * N + (size_t)c * NN_PER_BLOCK) * KD4;
#pragma unroll
    for (int nn = 0; nn < NN_PER_BLOCK; nn++) {
        float4* o = obase + (size_t)nn * KD4;
        o[t0] = v0;
        if (t1 < KD4) o[t1] = v1;
    }
}

// ------------------------------------------------------------------
extern "C" void kernel_launch(void* const* d_in, const int* in_sizes, int n_in,
                              void* d_out, int out_size) {
    const float* patches = (const float*)d_in[0];
    const float* adp     = (const float*)d_in[1];
    if (n_in >= 2 && in_sizes[0] == N * N && in_sizes[1] == B * N * P * D) {
        const float* t = patches; patches = adp; adp = t;
    }
    float* out = (float*)d_out;

    k_importance<<<128, 128>>>(adp);
    k_main<<<S * B * (P / 2) * 32 / 128, 128>>>(patches);   // 2048 CTAs
    k_finalize<<<B, 256>>>();
    k_out<<<B * (N / NN_PER_BLOCK), 256>>>(out);
}